// round 14
// baseline (speedup 1.0000x reference)
#include <cuda_runtime.h>
#include <cstdint>

// Problem constants
#define B_   8
#define C_   16
#define H_   128
#define W_   128
#define HW_  (H_*W_)
#define HID_ 128
#define NSTEPS_ 16
#define NPIX_  (B_*H_*W_)        // 131072
#define STATE_ (B_*C_*H_*W_)     // 2097152

// Scratch (no cudaMalloc allowed): ping-pong pre-gate state buffers
__device__ float g_buf0[STATE_];                      // 8 MB
__device__ float g_buf1[STATE_];                      // 8 MB
__device__ unsigned char g_mask[NSTEPS_ * NPIX_];     // 2 MB

// ---------------------------------------------------------------------------
// Threefry-2x32 (20 rounds) — exact JAX implementation (validated R5..R12)
// ---------------------------------------------------------------------------
__host__ __device__ __forceinline__ uint32_t rotl32(uint32_t v, int d) {
    return (v << d) | (v >> (32 - d));
}

__host__ __device__ inline void threefry2x32(uint32_t k0, uint32_t k1,
                                             uint32_t c0, uint32_t c1,
                                             uint32_t& o0, uint32_t& o1)
{
    uint32_t ks0 = k0, ks1 = k1, ks2 = k0 ^ k1 ^ 0x1BD11BDAu;
    uint32_t x0 = c0 + ks0;
    uint32_t x1 = c1 + ks1;
#define TF_RND(r) { x0 += x1; x1 = rotl32(x1, r); x1 ^= x0; }
    TF_RND(13) TF_RND(15) TF_RND(26) TF_RND(6)
    x0 += ks1; x1 += ks2 + 1u;
    TF_RND(17) TF_RND(29) TF_RND(16) TF_RND(24)
    x0 += ks2; x1 += ks0 + 2u;
    TF_RND(13) TF_RND(15) TF_RND(26) TF_RND(6)
    x0 += ks0; x1 += ks1 + 3u;
    TF_RND(17) TF_RND(29) TF_RND(16) TF_RND(24)
    x0 += ks1; x1 += ks2 + 4u;
    TF_RND(13) TF_RND(15) TF_RND(26) TF_RND(6)
    x0 += ks2; x1 += ks0 + 5u;
#undef TF_RND
    o0 = x0; o1 = x1;
}

struct Keys { uint32_t k0[NSTEPS_]; uint32_t k1[NSTEPS_]; };

__global__ void mask_kernel(Keys ka)
{
    unsigned gid = blockIdx.x * blockDim.x + threadIdx.x;
    unsigned s = gid >> 17;
    unsigned i = gid & (NPIX_ - 1);
    uint32_t o0, o1;
    threefry2x32(ka.k0[s], ka.k1[s], 0u, i, o0, o1);
    g_mask[gid] = (((o0 ^ o1) >> 31) == 0u) ? 1 : 0;
}

// ---------------------------------------------------------------------------
// Packed f32x2 helpers
// ---------------------------------------------------------------------------
__device__ __forceinline__ unsigned long long fma2(unsigned long long a,
                                                   unsigned long long b,
                                                   unsigned long long c)
{
    unsigned long long d;
    asm("fma.rn.f32x2 %0, %1, %2, %3;" : "=l"(d) : "l"(a), "l"(b), "l"(c));
    return d;
}
__device__ __forceinline__ unsigned long long pack2(float x, float y)
{
    unsigned long long r;
    asm("mov.b64 %0, {%1, %2};" : "=l"(r) : "f"(x), "f"(y));
    return r;
}
__device__ __forceinline__ float2 unpack2(unsigned long long v)
{
    float2 r;
    asm("mov.b64 {%0, %1}, %2;" : "=f"(r.x), "=f"(r.y) : "l"(v));
    return r;
}

// ---------------------------------------------------------------------------
// Step kernel (R10 core, best measured): one thread per vertical pixel pair.
//   w1 broadcast from SMEM (24 LDS.128/o-pair), w2 pair table (8 LDS.128),
//   layer1 acc lanes (hid o, o+1); layer2 acc lanes (hid-even, hid-odd),
//   cross-lane sum in epilogue.
// AL=true: source is the PREVIOUS step's pre-gate output; the alive gate
//   (3x3 max-pool of alpha > 0.1) is computed per thread and folded into the
//   12 stencil loads -> eliminates the standalone alive_kernel for steps 1..15.
// ---------------------------------------------------------------------------
template <bool AL>
__global__ void __launch_bounds__(128, 2) step_kernel(
    const float* __restrict__ xin,   // used when srcSel==0
    int srcSel,                      // 0: xin, 1: g_buf0, 2: g_buf1
    int dstSel,                      // 1: g_buf0, 2: g_buf1
    const float* __restrict__ w1g,   // (128, 48) row-major
    const float* __restrict__ b1g,   // (128,)
    const float* __restrict__ w2g,   // (16, 128) row-major
    const float* __restrict__ b2g,   // (16,)
    int step)
{
    const float* in  = (srcSel == 0) ? xin : (srcSel == 1 ? g_buf0 : g_buf1);
    float*       out = (dstSel == 1) ? g_buf0 : g_buf1;

    __shared__ __align__(16) float  w1s[HID_ * 48];  // 24 KB
    __shared__ __align__(16) float2 w2s[64 * 16];    // 8 KB: w2s[j*16+k] = (w2[k][2j], w2[k][2j+1])
    __shared__ __align__(8)  float  b1s[HID_];
    __shared__               float  b2s[16];

    const int tid = threadIdx.x;
#pragma unroll
    for (int i = 0; i < 48; ++i) w1s[i * 128 + tid] = w1g[i * 128 + tid];
    if (tid < HID_) b1s[tid] = b1g[tid];
    if (tid < 16)   b2s[tid] = b2g[tid];
    for (int i = tid; i < 64 * 16; i += 128) {
        int j = i >> 4, k = i & 15;
        w2s[j * 16 + k] = make_float2(w2g[k * HID_ + 2 * j], w2g[k * HID_ + 2 * j + 1]);
    }
    __syncthreads();

    const int x  = tid;
    const int y0 = 2 * blockIdx.x;
    const int b  = blockIdx.y;
    const bool xm = x > 0, xp = x < W_ - 1;
    const bool ym = y0 > 0;
    const bool yp = y0 < H_ - 2;
    const float* base = in + (((size_t)b * C_) * H_ + y0) * W_ + x;

    // Masks loaded early (latency overlap)
    const int pixA = (b * H_ + y0) * W_ + x;
    const float mA = (float)g_mask[step * NPIX_ + pixA];
    const float mB = (float)g_mask[step * NPIX_ + pixA + W_];

    // Alive flags for the 12 stencil positions: rows y0-1..y0+2, cols x-1..x+1.
    // alive(p) = (3x3 max of PRE-GATE alpha around p) > 0.1  (-inf padding).
    float af[4][3];
    if constexpr (AL) {
        const float* aP = in + (((size_t)b * C_ + 3) * H_) * W_;   // channel 3
        const float NEG = -3.0e38f;
        float a[6][5];   // alpha rows y0-2..y0+3, cols x-2..x+2
#pragma unroll
        for (int r = 0; r < 6; ++r) {
            int yy = y0 - 2 + r;
            bool yok = (yy >= 0) && (yy < H_);
#pragma unroll
            for (int c = 0; c < 5; ++c) {
                int xx = x - 2 + c;
                a[r][c] = (yok && xx >= 0 && xx < W_) ? aP[yy * W_ + xx] : NEG;
            }
        }
#pragma unroll
        for (int r = 0; r < 4; ++r) {
#pragma unroll
            for (int c = 0; c < 3; ++c) {
                float cm0 = fmaxf(fmaxf(a[r][c],     a[r + 1][c]),     a[r + 2][c]);
                float cm1 = fmaxf(fmaxf(a[r][c + 1], a[r + 1][c + 1]), a[r + 2][c + 1]);
                float cm2 = fmaxf(fmaxf(a[r][c + 2], a[r + 1][c + 2]), a[r + 2][c + 2]);
                af[r][c] = (fmaxf(fmaxf(cm0, cm1), cm2) > 0.1f) ? 1.f : 0.f;
            }
        }
    } else {
#pragma unroll
        for (int r = 0; r < 4; ++r)
#pragma unroll
            for (int c = 0; c < 3; ++c) af[r][c] = 1.f;   // constant-folds away
    }

    // Perception (channel-pair packed) for both pixels, alive-gated source.
    // layout: [0..7]=ident, [8..15]=sobel_x, [16..23]=sobel_y
    unsigned long long p2A[24], p2B[24];
#pragma unroll
    for (int c2 = 0; c2 < 8; ++c2) {
        float idA[2], gxA[2], gyA[2], idB[2], gxB[2], gyB[2];
#pragma unroll
        for (int h = 0; h < 2; ++h) {
            const float* q = base + (size_t)(2 * c2 + h) * HW_;
            float m1L = (ym && xm) ? q[-W_ - 1]  * af[0][0] : 0.f;
            float m1C =  ym        ? q[-W_]      * af[0][1] : 0.f;
            float m1R = (ym && xp) ? q[-W_ + 1]  * af[0][2] : 0.f;
            float r0L =  xm        ? q[-1]       * af[1][0] : 0.f;
            float r0C =              q[0]        * af[1][1];
            float r0R =  xp        ? q[1]        * af[1][2] : 0.f;
            float r1L =  xm        ? q[W_ - 1]   * af[2][0] : 0.f;
            float r1C =              q[W_]       * af[2][1];
            float r1R =  xp        ? q[W_ + 1]   * af[2][2] : 0.f;
            float r2L = (yp && xm) ? q[2*W_ - 1] * af[3][0] : 0.f;
            float r2C =  yp        ? q[2*W_]     * af[3][1] : 0.f;
            float r2R = (yp && xp) ? q[2*W_ + 1] * af[3][2] : 0.f;
            idA[h] = r0C;
            idB[h] = r1C;
            gxA[h] = ((m1L - m1R) + 2.f * (r0L - r0R) + (r1L - r1R)) * 0.125f;
            gyA[h] = ((m1L + 2.f * m1C + m1R) - (r1L + 2.f * r1C + r1R)) * 0.125f;
            gxB[h] = ((r0L - r0R) + 2.f * (r1L - r1R) + (r2L - r2R)) * 0.125f;
            gyB[h] = ((r0L + 2.f * r0C + r0R) - (r2L + 2.f * r2C + r2R)) * 0.125f;
        }
        p2A[c2]      = pack2(idA[0], idA[1]);
        p2A[8 + c2]  = pack2(gxA[0], gxA[1]);
        p2A[16 + c2] = pack2(gyA[0], gyA[1]);
        p2B[c2]      = pack2(idB[0], idB[1]);
        p2B[8 + c2]  = pack2(gxB[0], gxB[1]);
        p2B[16 + c2] = pack2(gyB[0], gyB[1]);
    }

    unsigned long long oaccA[16], oaccB[16];
#pragma unroll
    for (int k = 0; k < 16; ++k) { oaccA[k] = 0ull; oaccB[k] = 0ull; }

#pragma unroll 2
    for (int o = 0; o < HID_; o += 2) {
        const ulonglong2* r0 = reinterpret_cast<const ulonglong2*>(w1s + o * 48);
        const ulonglong2* r1 = reinterpret_cast<const ulonglong2*>(w1s + (o + 1) * 48);
        unsigned long long a0A = 0ull, a1A = 0ull, a0B = 0ull, a1B = 0ull;
#pragma unroll
        for (int q = 0; q < 12; ++q) {
            ulonglong2 wa = r0[q];          // LDS.128, uniform => broadcast
            ulonglong2 wb = r1[q];
            a0A = fma2(p2A[2 * q],     wa.x, a0A);
            a0A = fma2(p2A[2 * q + 1], wa.y, a0A);
            a1A = fma2(p2A[2 * q],     wb.x, a1A);
            a1A = fma2(p2A[2 * q + 1], wb.y, a1A);
            a0B = fma2(p2B[2 * q],     wa.x, a0B);
            a0B = fma2(p2B[2 * q + 1], wa.y, a0B);
            a1B = fma2(p2B[2 * q],     wb.x, a1B);
            a1B = fma2(p2B[2 * q + 1], wb.y, a1B);
        }
        float2 bb  = *reinterpret_cast<const float2*>(b1s + o);
        float2 avA = unpack2(a0A), bvA = unpack2(a1A);
        float2 avB = unpack2(a0B), bvB = unpack2(a1B);
        unsigned long long hpA = pack2(fmaxf(avA.x + avA.y + bb.x, 0.f),
                                       fmaxf(bvA.x + bvA.y + bb.y, 0.f));
        unsigned long long hpB = pack2(fmaxf(avB.x + avB.y + bb.x, 0.f),
                                       fmaxf(bvB.x + bvB.y + bb.y, 0.f));
        const ulonglong2* wr = reinterpret_cast<const ulonglong2*>(w2s + (o >> 1) * 16);
#pragma unroll
        for (int k2 = 0; k2 < 8; ++k2) {
            ulonglong2 w = wr[k2];
            oaccA[2 * k2]     = fma2(hpA, w.x, oaccA[2 * k2]);
            oaccA[2 * k2 + 1] = fma2(hpA, w.y, oaccA[2 * k2 + 1]);
            oaccB[2 * k2]     = fma2(hpB, w.x, oaccB[2 * k2]);
            oaccB[2 * k2 + 1] = fma2(hpB, w.y, oaccB[2 * k2 + 1]);
        }
    }

    // Epilogue: new = gated_state + diff*mask (PRE-GATE result stored to out)
    float* op = out + (((size_t)b * C_) * H_ + y0) * W_ + x;
#pragma unroll
    for (int k2 = 0; k2 < 8; ++k2) {
        float2 idA = unpack2(p2A[k2]);
        float2 idB = unpack2(p2B[k2]);
        float2 dA0 = unpack2(oaccA[2 * k2]);
        float2 dA1 = unpack2(oaccA[2 * k2 + 1]);
        float2 dB0 = unpack2(oaccB[2 * k2]);
        float2 dB1 = unpack2(oaccB[2 * k2 + 1]);
        float b2lo = b2s[2 * k2], b2hi = b2s[2 * k2 + 1];
        op[(size_t)(2 * k2) * HW_]          = idA.x + (dA0.x + dA0.y + b2lo) * mA;
        op[(size_t)(2 * k2 + 1) * HW_]      = idA.y + (dA1.x + dA1.y + b2hi) * mA;
        op[(size_t)(2 * k2) * HW_ + W_]     = idB.x + (dB0.x + dB0.y + b2lo) * mB;
        op[(size_t)(2 * k2 + 1) * HW_ + W_] = idB.y + (dB1.x + dB1.y + b2hi) * mB;
    }
}

// ---------------------------------------------------------------------------
// Final alive gating (runs ONCE after step 15): reads g_buf1 (pre-gate),
// writes gated state to d_out. Vectorized: 4 horizontal pixels / thread.
// ---------------------------------------------------------------------------
__global__ void __launch_bounds__(128) alive_kernel(float* __restrict__ state)
{
    const int t  = threadIdx.x;
    const int y  = blockIdx.x * 4 + (t >> 5);
    const int x0 = (t & 31) * 4;
    const int b  = blockIdx.y;
    const float* src = g_buf1;   // NSTEPS_=16 -> final pre-gate buffer is g_buf1

    const float* ap = src + ((((size_t)b * C_) + 3) * H_ + y) * W_;
    const float NEG = -3.0e38f;
    float c0 = NEG, c1 = NEG, c2 = NEG, c3 = NEG, c4 = NEG, c5 = NEG;
#pragma unroll
    for (int dy = -1; dy <= 1; ++dy) {
        int yy = y + dy;
        if (yy < 0 || yy >= H_) continue;
        const float* r = ap + dy * W_;
        float4 v = *reinterpret_cast<const float4*>(r + x0);
        float l  = (x0 > 0)      ? r[x0 - 1] : NEG;
        float rr = (x0 + 4 < W_) ? r[x0 + 4] : NEG;
        c0 = fmaxf(c0, l);
        c1 = fmaxf(c1, v.x);
        c2 = fmaxf(c2, v.y);
        c3 = fmaxf(c3, v.z);
        c4 = fmaxf(c4, v.w);
        c5 = fmaxf(c5, rr);
    }
    float4 alive;
    alive.x = (fmaxf(fmaxf(c0, c1), c2) > 0.1f) ? 1.f : 0.f;
    alive.y = (fmaxf(fmaxf(c1, c2), c3) > 0.1f) ? 1.f : 0.f;
    alive.z = (fmaxf(fmaxf(c2, c3), c4) > 0.1f) ? 1.f : 0.f;
    alive.w = (fmaxf(fmaxf(c3, c4), c5) > 0.1f) ? 1.f : 0.f;

    const float* np = src + (((size_t)b * C_) * H_ + y) * W_ + x0;
    float* sp = state + (((size_t)b * C_) * H_ + y) * W_ + x0;
#pragma unroll
    for (int k = 0; k < C_; ++k) {
        float4 v = *reinterpret_cast<const float4*>(np + (size_t)k * HW_);
        v.x *= alive.x; v.y *= alive.y; v.z *= alive.z; v.w *= alive.w;
        *reinterpret_cast<float4*>(sp + (size_t)k * HW_) = v;
    }
}

// ---------------------------------------------------------------------------
extern "C" void kernel_launch(void* const* d_in, const int* in_sizes, int n_in,
                              void* d_out, int out_size)
{
    (void)in_sizes; (void)n_in; (void)out_size;
    const float* x  = (const float*)d_in[0];
    const float* w1 = (const float*)d_in[1];
    const float* b1 = (const float*)d_in[2];
    const float* w2 = (const float*)d_in[3];
    const float* b2 = (const float*)d_in[4];
    float* state = (float*)d_out;

    Keys ka;
    for (int s = 0; s < NSTEPS_; ++s) {
        uint32_t o0, o1;
        threefry2x32(0u, 42u, 0u, (uint32_t)s, o0, o1);
        ka.k0[s] = o0; ka.k1[s] = o1;
    }

    mask_kernel<<<(NSTEPS_ * NPIX_) / 256, 256>>>(ka);

    // Step 0: read raw input (no gate), write pre-gate to g_buf0.
    step_kernel<false><<<dim3(H_ / 2, B_), 128>>>(x, 0, 1, w1, b1, w2, b2, 0);
    // Steps 1..15: read previous pre-gate buffer with alive gate fused in.
    for (int s = 1; s < NSTEPS_; ++s) {
        int srcSel = ((s - 1) & 1) + 1;   // buf written by s-1
        int dstSel = (s & 1) + 1;
        step_kernel<true><<<dim3(H_ / 2, B_), 128>>>(nullptr, srcSel, dstSel,
                                                     w1, b1, w2, b2, s);
    }
    // Final gate: g_buf1 -> d_out.
    alive_kernel<<<dim3(H_ / 4, B_), 128>>>(state);
}

// round 15
// speedup vs baseline: 1.0779x; 1.0779x over previous
#include <cuda_runtime.h>
#include <cstdint>

// Problem constants
#define B_   8
#define C_   16
#define H_   128
#define W_   128
#define HW_  (H_*W_)
#define HID_ 128
#define NSTEPS_ 16
#define NPIX_  (B_*H_*W_)        // 131072
#define STATE_ (B_*C_*H_*W_)     // 2097152

// Scratch (no cudaMalloc allowed)
__device__ float g_new[STATE_];                       // 8 MB: pre-gate state
__device__ unsigned char g_mask[NSTEPS_ * NPIX_];     // 2 MB: precomputed threefry masks

// ---------------------------------------------------------------------------
// Threefry-2x32 (20 rounds) — exact JAX implementation (validated R5..R14)
// ---------------------------------------------------------------------------
__host__ __device__ __forceinline__ uint32_t rotl32(uint32_t v, int d) {
    return (v << d) | (v >> (32 - d));
}

__host__ __device__ inline void threefry2x32(uint32_t k0, uint32_t k1,
                                             uint32_t c0, uint32_t c1,
                                             uint32_t& o0, uint32_t& o1)
{
    uint32_t ks0 = k0, ks1 = k1, ks2 = k0 ^ k1 ^ 0x1BD11BDAu;
    uint32_t x0 = c0 + ks0;
    uint32_t x1 = c1 + ks1;
#define TF_RND(r) { x0 += x1; x1 = rotl32(x1, r); x1 ^= x0; }
    TF_RND(13) TF_RND(15) TF_RND(26) TF_RND(6)
    x0 += ks1; x1 += ks2 + 1u;
    TF_RND(17) TF_RND(29) TF_RND(16) TF_RND(24)
    x0 += ks2; x1 += ks0 + 2u;
    TF_RND(13) TF_RND(15) TF_RND(26) TF_RND(6)
    x0 += ks0; x1 += ks1 + 3u;
    TF_RND(17) TF_RND(29) TF_RND(16) TF_RND(24)
    x0 += ks1; x1 += ks2 + 4u;
    TF_RND(13) TF_RND(15) TF_RND(26) TF_RND(6)
    x0 += ks2; x1 += ks0 + 5u;
#undef TF_RND
    o0 = x0; o1 = x1;
}

struct Keys { uint32_t k0[NSTEPS_]; uint32_t k1[NSTEPS_]; };

__global__ void mask_kernel(Keys ka)
{
    unsigned gid = blockIdx.x * blockDim.x + threadIdx.x;
    unsigned s = gid >> 17;
    unsigned i = gid & (NPIX_ - 1);
    uint32_t o0, o1;
    threefry2x32(ka.k0[s], ka.k1[s], 0u, i, o0, o1);
    g_mask[gid] = (((o0 ^ o1) >> 31) == 0u) ? 1 : 0;
}

// ---------------------------------------------------------------------------
// Packed f32x2 helpers
// ---------------------------------------------------------------------------
__device__ __forceinline__ unsigned long long fma2(unsigned long long a,
                                                   unsigned long long b,
                                                   unsigned long long c)
{
    unsigned long long d;
    asm("fma.rn.f32x2 %0, %1, %2, %3;" : "=l"(d) : "l"(a), "l"(b), "l"(c));
    return d;
}
__device__ __forceinline__ unsigned long long pack2(float x, float y)
{
    unsigned long long r;
    asm("mov.b64 %0, {%1, %2};" : "=l"(r) : "f"(x), "f"(y));
    return r;
}
__device__ __forceinline__ float2 unpack2(unsigned long long v)
{
    float2 r;
    asm("mov.b64 {%0, %1}, %2;" : "=f"(r.x), "=f"(r.y) : "l"(v));
    return r;
}

// ---------------------------------------------------------------------------
// Step kernel — EXACT R10 core (best measured step: 80.9 us ncu).
// One thread per vertical pixel pair (y0, y0+1). w1 broadcast from SMEM
// (24 LDS.128/o-pair), w2 pair table (8 LDS.128). Layer1 acc lanes
// (hid o, o+1); layer2 acc lanes (hid-even, hid-odd), cross-lane sum in
// epilogue. Reads `state` (post-gate), writes pre-gate to g_new.
// ---------------------------------------------------------------------------
__global__ void __launch_bounds__(128) step_kernel(
    const float* __restrict__ in,
    const float* __restrict__ w1g,   // (128, 48) row-major
    const float* __restrict__ b1g,   // (128,)
    const float* __restrict__ w2g,   // (16, 128) row-major
    const float* __restrict__ b2g,   // (16,)
    int step)
{
    __shared__ __align__(16) float  w1s[HID_ * 48];  // 24 KB
    __shared__ __align__(16) float2 w2s[64 * 16];    // 8 KB: w2s[j*16+k] = (w2[k][2j], w2[k][2j+1])
    __shared__ __align__(8)  float  b1s[HID_];
    __shared__               float  b2s[16];

    const int tid = threadIdx.x;
#pragma unroll
    for (int i = 0; i < 48; ++i) w1s[i * 128 + tid] = w1g[i * 128 + tid];
    if (tid < HID_) b1s[tid] = b1g[tid];
    if (tid < 16)   b2s[tid] = b2g[tid];
    for (int i = tid; i < 64 * 16; i += 128) {
        int j = i >> 4, k = i & 15;
        w2s[j * 16 + k] = make_float2(w2g[k * HID_ + 2 * j], w2g[k * HID_ + 2 * j + 1]);
    }
    __syncthreads();

    const int x  = tid;
    const int y0 = 2 * blockIdx.x;
    const int b  = blockIdx.y;
    const bool xm = x > 0, xp = x < W_ - 1;
    const bool ym = y0 > 0;
    const bool yp = y0 < H_ - 2;
    const float* base = in + (((size_t)b * C_) * H_ + y0) * W_ + x;

    // Perception (channel-pair packed) for both pixels.
    // layout: [0..7]=ident, [8..15]=sobel_x, [16..23]=sobel_y
    unsigned long long p2A[24], p2B[24];
#pragma unroll
    for (int c2 = 0; c2 < 8; ++c2) {
        float idA[2], gxA[2], gyA[2], idB[2], gxB[2], gyB[2];
#pragma unroll
        for (int h = 0; h < 2; ++h) {
            const float* q = base + (size_t)(2 * c2 + h) * HW_;
            float m1L = (ym && xm) ? q[-W_ - 1]  : 0.f;
            float m1C =  ym        ? q[-W_]      : 0.f;
            float m1R = (ym && xp) ? q[-W_ + 1]  : 0.f;
            float r0L =  xm        ? q[-1]       : 0.f;
            float r0C =              q[0];
            float r0R =  xp        ? q[1]        : 0.f;
            float r1L =  xm        ? q[W_ - 1]   : 0.f;
            float r1C =              q[W_];
            float r1R =  xp        ? q[W_ + 1]   : 0.f;
            float r2L = (yp && xm) ? q[2*W_ - 1] : 0.f;
            float r2C =  yp        ? q[2*W_]     : 0.f;
            float r2R = (yp && xp) ? q[2*W_ + 1] : 0.f;
            idA[h] = r0C;
            idB[h] = r1C;
            gxA[h] = ((m1L - m1R) + 2.f * (r0L - r0R) + (r1L - r1R)) * 0.125f;
            gyA[h] = ((m1L + 2.f * m1C + m1R) - (r1L + 2.f * r1C + r1R)) * 0.125f;
            gxB[h] = ((r0L - r0R) + 2.f * (r1L - r1R) + (r2L - r2R)) * 0.125f;
            gyB[h] = ((r0L + 2.f * r0C + r0R) - (r2L + 2.f * r2C + r2R)) * 0.125f;
        }
        p2A[c2]      = pack2(idA[0], idA[1]);
        p2A[8 + c2]  = pack2(gxA[0], gxA[1]);
        p2A[16 + c2] = pack2(gyA[0], gyA[1]);
        p2B[c2]      = pack2(idB[0], idB[1]);
        p2B[8 + c2]  = pack2(gxB[0], gxB[1]);
        p2B[16 + c2] = pack2(gyB[0], gyB[1]);
    }

    unsigned long long oaccA[16], oaccB[16];
#pragma unroll
    for (int k = 0; k < 16; ++k) { oaccA[k] = 0ull; oaccB[k] = 0ull; }

#pragma unroll 2
    for (int o = 0; o < HID_; o += 2) {
        const ulonglong2* r0 = reinterpret_cast<const ulonglong2*>(w1s + o * 48);
        const ulonglong2* r1 = reinterpret_cast<const ulonglong2*>(w1s + (o + 1) * 48);
        unsigned long long a0A = 0ull, a1A = 0ull, a0B = 0ull, a1B = 0ull;
#pragma unroll
        for (int q = 0; q < 12; ++q) {
            ulonglong2 wa = r0[q];          // LDS.128, uniform => broadcast
            ulonglong2 wb = r1[q];
            a0A = fma2(p2A[2 * q],     wa.x, a0A);
            a0A = fma2(p2A[2 * q + 1], wa.y, a0A);
            a1A = fma2(p2A[2 * q],     wb.x, a1A);
            a1A = fma2(p2A[2 * q + 1], wb.y, a1A);
            a0B = fma2(p2B[2 * q],     wa.x, a0B);
            a0B = fma2(p2B[2 * q + 1], wa.y, a0B);
            a1B = fma2(p2B[2 * q],     wb.x, a1B);
            a1B = fma2(p2B[2 * q + 1], wb.y, a1B);
        }
        float2 bb  = *reinterpret_cast<const float2*>(b1s + o);
        float2 avA = unpack2(a0A), bvA = unpack2(a1A);
        float2 avB = unpack2(a0B), bvB = unpack2(a1B);
        unsigned long long hpA = pack2(fmaxf(avA.x + avA.y + bb.x, 0.f),
                                       fmaxf(bvA.x + bvA.y + bb.y, 0.f));
        unsigned long long hpB = pack2(fmaxf(avB.x + avB.y + bb.x, 0.f),
                                       fmaxf(bvB.x + bvB.y + bb.y, 0.f));
        const ulonglong2* wr = reinterpret_cast<const ulonglong2*>(w2s + (o >> 1) * 16);
#pragma unroll
        for (int k2 = 0; k2 < 8; ++k2) {
            ulonglong2 w = wr[k2];
            oaccA[2 * k2]     = fma2(hpA, w.x, oaccA[2 * k2]);
            oaccA[2 * k2 + 1] = fma2(hpA, w.y, oaccA[2 * k2 + 1]);
            oaccB[2 * k2]     = fma2(hpB, w.x, oaccB[2 * k2]);
            oaccB[2 * k2 + 1] = fma2(hpB, w.y, oaccB[2 * k2 + 1]);
        }
    }

    const int pixA = (b * H_ + y0) * W_ + x;
    const float mA = (float)g_mask[step * NPIX_ + pixA];
    const float mB = (float)g_mask[step * NPIX_ + pixA + W_];
    float* opA = g_new + (((size_t)b * C_) * H_ + y0) * W_ + x;
#pragma unroll
    for (int k2 = 0; k2 < 8; ++k2) {
        float2 idA = unpack2(p2A[k2]);
        float2 idB = unpack2(p2B[k2]);
        float2 dA0 = unpack2(oaccA[2 * k2]);
        float2 dA1 = unpack2(oaccA[2 * k2 + 1]);
        float2 dB0 = unpack2(oaccB[2 * k2]);
        float2 dB1 = unpack2(oaccB[2 * k2 + 1]);
        float b2lo = b2s[2 * k2], b2hi = b2s[2 * k2 + 1];
        opA[(size_t)(2 * k2) * HW_]          = idA.x + (dA0.x + dA0.y + b2lo) * mA;
        opA[(size_t)(2 * k2 + 1) * HW_]      = idA.y + (dA1.x + dA1.y + b2hi) * mA;
        opA[(size_t)(2 * k2) * HW_ + W_]     = idB.x + (dB0.x + dB0.y + b2lo) * mB;
        opA[(size_t)(2 * k2 + 1) * HW_ + W_] = idB.y + (dB1.x + dB1.y + b2hi) * mB;
    }
}

// ---------------------------------------------------------------------------
// Alive gating, vectorized (R11-style, measured good): 4 horizontal pixels
// per thread (float4). pooled = 3x3 max of alpha (ch 3, -inf pad);
// state = g_new * (pooled > 0.1). Runs after every step.
// ---------------------------------------------------------------------------
__global__ void __launch_bounds__(128) alive_kernel(float* __restrict__ state)
{
    const int t  = threadIdx.x;
    const int y  = blockIdx.x * 4 + (t >> 5);
    const int x0 = (t & 31) * 4;
    const int b  = blockIdx.y;

    const float* ap = g_new + ((((size_t)b * C_) + 3) * H_ + y) * W_;
    const float NEG = -3.0e38f;
    float c0 = NEG, c1 = NEG, c2 = NEG, c3 = NEG, c4 = NEG, c5 = NEG;
#pragma unroll
    for (int dy = -1; dy <= 1; ++dy) {
        int yy = y + dy;
        if (yy < 0 || yy >= H_) continue;
        const float* r = ap + dy * W_;
        float4 v = *reinterpret_cast<const float4*>(r + x0);
        float l  = (x0 > 0)      ? r[x0 - 1] : NEG;
        float rr = (x0 + 4 < W_) ? r[x0 + 4] : NEG;
        c0 = fmaxf(c0, l);
        c1 = fmaxf(c1, v.x);
        c2 = fmaxf(c2, v.y);
        c3 = fmaxf(c3, v.z);
        c4 = fmaxf(c4, v.w);
        c5 = fmaxf(c5, rr);
    }
    float4 alive;
    alive.x = (fmaxf(fmaxf(c0, c1), c2) > 0.1f) ? 1.f : 0.f;
    alive.y = (fmaxf(fmaxf(c1, c2), c3) > 0.1f) ? 1.f : 0.f;
    alive.z = (fmaxf(fmaxf(c2, c3), c4) > 0.1f) ? 1.f : 0.f;
    alive.w = (fmaxf(fmaxf(c3, c4), c5) > 0.1f) ? 1.f : 0.f;

    const float* np = g_new + (((size_t)b * C_) * H_ + y) * W_ + x0;
    float* sp = state + (((size_t)b * C_) * H_ + y) * W_ + x0;
#pragma unroll
    for (int k = 0; k < C_; ++k) {
        float4 v = *reinterpret_cast<const float4*>(np + (size_t)k * HW_);
        v.x *= alive.x; v.y *= alive.y; v.z *= alive.z; v.w *= alive.w;
        *reinterpret_cast<float4*>(sp + (size_t)k * HW_) = v;
    }
}

// ---------------------------------------------------------------------------
extern "C" void kernel_launch(void* const* d_in, const int* in_sizes, int n_in,
                              void* d_out, int out_size)
{
    (void)in_sizes; (void)n_in; (void)out_size;
    const float* x  = (const float*)d_in[0];
    const float* w1 = (const float*)d_in[1];
    const float* b1 = (const float*)d_in[2];
    const float* w2 = (const float*)d_in[3];
    const float* b2 = (const float*)d_in[4];
    float* state = (float*)d_out;

    Keys ka;
    for (int s = 0; s < NSTEPS_; ++s) {
        uint32_t o0, o1;
        threefry2x32(0u, 42u, 0u, (uint32_t)s, o0, o1);
        ka.k0[s] = o0; ka.k1[s] = o1;
    }

    cudaMemcpyAsync(state, x, STATE_ * sizeof(float), cudaMemcpyDeviceToDevice);
    mask_kernel<<<(NSTEPS_ * NPIX_) / 256, 256>>>(ka);
    for (int s = 0; s < NSTEPS_; ++s) {
        step_kernel<<<dim3(H_ / 2, B_), 128>>>(state, w1, b1, w2, b2, s);
        alive_kernel<<<dim3(H_ / 4, B_), 128>>>(state);
    }
}

// round 17
// speedup vs baseline: 1.4409x; 1.3368x over previous
#include <cuda_runtime.h>
#include <cstdint>

// Problem constants
#define B_   8
#define C_   16
#define H_   128
#define W_   128
#define HW_  (H_*W_)
#define HID_ 128
#define NSTEPS_ 16
#define NPIX_  (B_*H_*W_)        // 131072
#define STATE_ (B_*C_*H_*W_)     // 2097152

// Scratch (no cudaMalloc allowed)
__device__ float g_new[STATE_];                   // 8 MB: pre-gate state
__device__ int   g_list[NSTEPS_][NPIX_];          // 8 MB: active-pixel lists
__device__ unsigned int g_count[NSTEPS_];         // active counts per step

// Safe upper bound on active pixels (mean 65536, sigma ~181; +90 sigma)
#define MAXACT_ 81920

// ---------------------------------------------------------------------------
// Threefry-2x32 (20 rounds) — exact JAX implementation (validated R5..R15)
// ---------------------------------------------------------------------------
__host__ __device__ __forceinline__ uint32_t rotl32(uint32_t v, int d) {
    return (v << d) | (v >> (32 - d));
}

__host__ __device__ inline void threefry2x32(uint32_t k0, uint32_t k1,
                                             uint32_t c0, uint32_t c1,
                                             uint32_t& o0, uint32_t& o1)
{
    uint32_t ks0 = k0, ks1 = k1, ks2 = k0 ^ k1 ^ 0x1BD11BDAu;
    uint32_t x0 = c0 + ks0;
    uint32_t x1 = c1 + ks1;
#define TF_RND(r) { x0 += x1; x1 = rotl32(x1, r); x1 ^= x0; }
    TF_RND(13) TF_RND(15) TF_RND(26) TF_RND(6)
    x0 += ks1; x1 += ks2 + 1u;
    TF_RND(17) TF_RND(29) TF_RND(16) TF_RND(24)
    x0 += ks2; x1 += ks0 + 2u;
    TF_RND(13) TF_RND(15) TF_RND(26) TF_RND(6)
    x0 += ks0; x1 += ks1 + 3u;
    TF_RND(17) TF_RND(29) TF_RND(16) TF_RND(24)
    x0 += ks1; x1 += ks2 + 4u;
    TF_RND(13) TF_RND(15) TF_RND(26) TF_RND(6)
    x0 += ks2; x1 += ks0 + 5u;
#undef TF_RND
    o0 = x0; o1 = x1;
}

struct Keys { uint32_t k0[NSTEPS_]; uint32_t k1[NSTEPS_]; };

// ---------------------------------------------------------------------------
// Mask + compaction in one kernel: computes the threefry mask bit and appends
// active pixel indices to g_list[s] (warp-granular order => good locality).
// List order is nondeterministic across blocks, but every pixel's result is
// independent of processing order => output deterministic.
// ---------------------------------------------------------------------------
__global__ void mask_compact_kernel(Keys ka)
{
    const int s = blockIdx.y;
    const unsigned i = blockIdx.x * 256 + threadIdx.x;   // pixel index
    uint32_t o0, o1;
    threefry2x32(ka.k0[s], ka.k1[s], 0u, i, o0, o1);
    const bool active = (((o0 ^ o1) >> 31) == 0u);

    const unsigned lane = threadIdx.x & 31;
    unsigned bal = __ballot_sync(0xffffffffu, active);
    int rank  = __popc(bal & ((1u << lane) - 1u));
    int total = __popc(bal);
    unsigned base = 0;
    if (lane == 0 && total > 0) base = atomicAdd(&g_count[s], (unsigned)total);
    base = __shfl_sync(0xffffffffu, base, 0);
    if (active) g_list[s][base + rank] = (int)i;
}

// ---------------------------------------------------------------------------
// Packed f32x2 helpers
// ---------------------------------------------------------------------------
__device__ __forceinline__ unsigned long long fma2(unsigned long long a,
                                                   unsigned long long b,
                                                   unsigned long long c)
{
    unsigned long long d;
    asm("fma.rn.f32x2 %0, %1, %2, %3;" : "=l"(d) : "l"(a), "l"(b), "l"(c));
    return d;
}
__device__ __forceinline__ unsigned long long pack2(float x, float y)
{
    unsigned long long r;
    asm("mov.b64 %0, {%1, %2};" : "=l"(r) : "f"(x), "f"(y));
    return r;
}
__device__ __forceinline__ float2 unpack2(unsigned long long v)
{
    float2 r;
    asm("mov.b64 {%0, %1}, %2;" : "=f"(r.x), "=f"(r.y) : "l"(v));
    return r;
}

// ---------------------------------------------------------------------------
// Compacted step kernel: ONE ACTIVE PIXEL PER THREAD (mask==1 guaranteed,
// so the mask multiply disappears and only ~50% of pixels run the MLP).
// w1 broadcast from SMEM (24 LDS.128/o-pair); layer2 lane-packed:
// acc[j] lanes = (out 2j, out 2j+1), w2p[hid][j] = (w2[2j][hid], w2[2j+1][hid]).
// Low registers (~110) => __launch_bounds__(128,4): 16 warps/SM.
// Inactive pixels are pre-seeded by the g_new <- state copy.
// ---------------------------------------------------------------------------
__global__ void __launch_bounds__(128, 4) step_kernel(
    const float* __restrict__ in,
    const float* __restrict__ w1g,   // (128, 48) row-major
    const float* __restrict__ b1g,   // (128,)
    const float* __restrict__ w2g,   // (16, 128) row-major
    const float* __restrict__ b2g,   // (16,)
    int step)
{
    __shared__ __align__(16) float          w1s[HID_ * 48];   // 24 KB
    __shared__ __align__(16) unsigned long long w2p[HID_ * 8]; // 8 KB
    __shared__ __align__(8)  float          b1s[HID_];
    __shared__               float          b2s[16];

    const int tid = threadIdx.x;
#pragma unroll
    for (int i = 0; i < 48; ++i) w1s[i * 128 + tid] = w1g[i * 128 + tid];
    if (tid < HID_) b1s[tid] = b1g[tid];
    if (tid < 16)   b2s[tid] = b2g[tid];
    for (int i = tid; i < HID_ * 8; i += 128) {
        int h = i >> 3, j = i & 7;
        w2p[i] = pack2(w2g[(2 * j) * HID_ + h], w2g[(2 * j + 1) * HID_ + h]);
    }
    __syncthreads();

    const int gid = blockIdx.x * 128 + tid;
    if (gid >= (int)g_count[step]) return;
    const int pix = g_list[step][gid];
    const int b = pix >> 14;
    const int y = (pix >> 7) & 127;
    const int x = pix & 127;

    const bool xm = x > 0, xp = x < W_ - 1, ym = y > 0, yp = y < H_ - 1;
    const float* base = in + (((size_t)b * C_) * H_ + y) * W_ + x;

    // Perception packed in channel pairs: p2[0..7]=ident, [8..15]=sx, [16..23]=sy
    unsigned long long p2[24];
#pragma unroll
    for (int c2 = 0; c2 < 8; ++c2) {
        float idv[2], gx[2], gy[2];
#pragma unroll
        for (int h = 0; h < 2; ++h) {
            const float* q = base + (size_t)(2 * c2 + h) * HW_;
            float a00 = (ym && xm) ? q[-W_ - 1] : 0.f;
            float a01 =  ym        ? q[-W_]     : 0.f;
            float a02 = (ym && xp) ? q[-W_ + 1] : 0.f;
            float a10 =  xm        ? q[-1]      : 0.f;
            float a11 =              q[0];
            float a12 =  xp        ? q[1]       : 0.f;
            float a20 = (yp && xm) ? q[W_ - 1]  : 0.f;
            float a21 =  yp        ? q[W_]      : 0.f;
            float a22 = (yp && xp) ? q[W_ + 1]  : 0.f;
            idv[h] = a11;
            gx[h] = ((a00 - a02) + 2.f * (a10 - a12) + (a20 - a22)) * 0.125f;
            gy[h] = ((a00 + 2.f * a01 + a02) - (a20 + 2.f * a21 + a22)) * 0.125f;
        }
        p2[c2]      = pack2(idv[0], idv[1]);
        p2[8 + c2]  = pack2(gx[0], gx[1]);
        p2[16 + c2] = pack2(gy[0], gy[1]);
    }

    // Layer2 accumulators: acc[j] lanes = (out 2j, out 2j+1)
    unsigned long long acc[8];
#pragma unroll
    for (int j = 0; j < 8; ++j) acc[j] = 0ull;

#pragma unroll 2
    for (int o = 0; o < HID_; o += 2) {
        const ulonglong2* r0 = reinterpret_cast<const ulonglong2*>(w1s + o * 48);
        const ulonglong2* r1 = reinterpret_cast<const ulonglong2*>(w1s + (o + 1) * 48);
        unsigned long long a0 = 0ull, a1 = 0ull;
#pragma unroll
        for (int q = 0; q < 12; ++q) {
            ulonglong2 wa = r0[q];          // LDS.128, uniform => broadcast
            ulonglong2 wb = r1[q];
            a0 = fma2(p2[2 * q],     wa.x, a0);
            a0 = fma2(p2[2 * q + 1], wa.y, a0);
            a1 = fma2(p2[2 * q],     wb.x, a1);
            a1 = fma2(p2[2 * q + 1], wb.y, a1);
        }
        float2 bb = *reinterpret_cast<const float2*>(b1s + o);
        float2 av = unpack2(a0), bv = unpack2(a1);
        float h0 = fmaxf(av.x + av.y + bb.x, 0.f);
        float h1 = fmaxf(bv.x + bv.y + bb.y, 0.f);
        unsigned long long hp0 = pack2(h0, h0);
        unsigned long long hp1 = pack2(h1, h1);
        const ulonglong2* wr0 = reinterpret_cast<const ulonglong2*>(w2p + o * 8);
        const ulonglong2* wr1 = reinterpret_cast<const ulonglong2*>(w2p + (o + 1) * 8);
#pragma unroll
        for (int j2 = 0; j2 < 4; ++j2) {
            ulonglong2 wA = wr0[j2];
            ulonglong2 wB = wr1[j2];
            acc[2 * j2]     = fma2(hp0, wA.x, acc[2 * j2]);
            acc[2 * j2 + 1] = fma2(hp0, wA.y, acc[2 * j2 + 1]);
            acc[2 * j2]     = fma2(hp1, wB.x, acc[2 * j2]);
            acc[2 * j2 + 1] = fma2(hp1, wB.y, acc[2 * j2 + 1]);
        }
    }

    // Epilogue: active pixel => mask==1 => new = ident + diff
    float* op = g_new + (((size_t)b * C_) * H_ + y) * W_ + x;
#pragma unroll
    for (int j = 0; j < 8; ++j) {
        float2 idv = unpack2(p2[j]);
        float2 d   = unpack2(acc[j]);
        op[(size_t)(2 * j) * HW_]     = idv.x + d.x + b2s[2 * j];
        op[(size_t)(2 * j + 1) * HW_] = idv.y + d.y + b2s[2 * j + 1];
    }
}

// ---------------------------------------------------------------------------
// Alive gating, vectorized (unchanged, measured good): 4 px/thread (float4).
// pooled = 3x3 max of alpha (ch 3, -inf pad); state = g_new * (pooled > 0.1)
// ---------------------------------------------------------------------------
__global__ void __launch_bounds__(128) alive_kernel(float* __restrict__ state)
{
    const int t  = threadIdx.x;
    const int y  = blockIdx.x * 4 + (t >> 5);
    const int x0 = (t & 31) * 4;
    const int b  = blockIdx.y;

    const float* ap = g_new + ((((size_t)b * C_) + 3) * H_ + y) * W_;
    const float NEG = -3.0e38f;
    float c0 = NEG, c1 = NEG, c2 = NEG, c3 = NEG, c4 = NEG, c5 = NEG;
#pragma unroll
    for (int dy = -1; dy <= 1; ++dy) {
        int yy = y + dy;
        if (yy < 0 || yy >= H_) continue;
        const float* r = ap + dy * W_;
        float4 v = *reinterpret_cast<const float4*>(r + x0);
        float l  = (x0 > 0)      ? r[x0 - 1] : NEG;
        float rr = (x0 + 4 < W_) ? r[x0 + 4] : NEG;
        c0 = fmaxf(c0, l);
        c1 = fmaxf(c1, v.x);
        c2 = fmaxf(c2, v.y);
        c3 = fmaxf(c3, v.z);
        c4 = fmaxf(c4, v.w);
        c5 = fmaxf(c5, rr);
    }
    float4 alive;
    alive.x = (fmaxf(fmaxf(c0, c1), c2) > 0.1f) ? 1.f : 0.f;
    alive.y = (fmaxf(fmaxf(c1, c2), c3) > 0.1f) ? 1.f : 0.f;
    alive.z = (fmaxf(fmaxf(c2, c3), c4) > 0.1f) ? 1.f : 0.f;
    alive.w = (fmaxf(fmaxf(c3, c4), c5) > 0.1f) ? 1.f : 0.f;

    const float* np = g_new + (((size_t)b * C_) * H_ + y) * W_ + x0;
    float* sp = state + (((size_t)b * C_) * H_ + y) * W_ + x0;
#pragma unroll
    for (int k = 0; k < C_; ++k) {
        float4 v = *reinterpret_cast<const float4*>(np + (size_t)k * HW_);
        v.x *= alive.x; v.y *= alive.y; v.z *= alive.z; v.w *= alive.w;
        *reinterpret_cast<float4*>(sp + (size_t)k * HW_) = v;
    }
}

// ---------------------------------------------------------------------------
extern "C" void kernel_launch(void* const* d_in, const int* in_sizes, int n_in,
                              void* d_out, int out_size)
{
    (void)in_sizes; (void)n_in; (void)out_size;
    const float* x  = (const float*)d_in[0];
    const float* w1 = (const float*)d_in[1];
    const float* b1 = (const float*)d_in[2];
    const float* w2 = (const float*)d_in[3];
    const float* b2 = (const float*)d_in[4];
    float* state = (float*)d_out;

    Keys ka;
    for (int s = 0; s < NSTEPS_; ++s) {
        uint32_t o0, o1;
        threefry2x32(0u, 42u, 0u, (uint32_t)s, o0, o1);
        ka.k0[s] = o0; ka.k1[s] = o1;
    }

    void *p_new = nullptr, *p_count = nullptr;
    cudaGetSymbolAddress(&p_new, g_new);
    cudaGetSymbolAddress(&p_count, g_count);

    cudaMemcpyAsync(state, x, STATE_ * sizeof(float), cudaMemcpyDeviceToDevice);
    cudaMemsetAsync(p_count, 0, NSTEPS_ * sizeof(unsigned int));   // reset per replay
    mask_compact_kernel<<<dim3(NPIX_ / 256, NSTEPS_), 256>>>(ka);

    for (int s = 0; s < NSTEPS_; ++s) {
        // Seed inactive pixels: g_new starts as a copy of current state.
        cudaMemcpyAsync(p_new, state, STATE_ * sizeof(float),
                        cudaMemcpyDeviceToDevice);
        step_kernel<<<MAXACT_ / 128, 128>>>(state, w1, b1, w2, b2, s);
        alive_kernel<<<dim3(H_ / 4, B_), 128>>>(state);
    }
}